// round 10
// baseline (speedup 1.0000x reference)
#include <cuda_runtime.h>
#include <cuda_bf16.h>
#include <cstdint>

#define OUTF   11008
#define INF    4096
#define BATCHN 16
#define SPLITK 32
#define KC     (INF / SPLITK)        // 128 k per CTA
#define KTILE  16                    // k per pipeline stage == one MMA k-step
#define NSTAGE (KC / KTILE)          // 8 stages
#define OTILE  256                   // output rows per CTA (8 warps x 32 rows)
#define NTHR   256
#define WROW   20                    // ints per smem W row (16 data + 4 pad; 80B, 16B-aligned)
#define WBUF   (OTILE * WROW)        // 5120 ints per buffer
#define XSTR   68                    // words per xs row (64 data + 4 pad)
#define XWORDS (16 * XSTR)
#define STAGE_BYTES (OTILE * KTILE * 4)          // 16384 actual bytes per stage
// layout: [0:32) mbarriers+pad | W bufs | x planes
#define SMEM_BYTES (32 + 2 * WBUF * 4 + 2 * XWORDS * 4)   // 32+40960+8704 = 49696

// Split-K partials: [SPLITK][BATCHN][OUTF] = 22.5 MB
__device__ float g_partial[SPLITK * BATCHN * OUTF];
// Phase-1 reduced partials: [8][BATCHN][OUTF]
__device__ float g_p2[8 * BATCHN * OUTF];

__device__ __forceinline__ uint32_t pack_bf16x2(float lo, float hi) {
    uint32_t r;
    asm("cvt.rn.bf16x2.f32 %0, %1, %2;" : "=r"(r) : "f"(hi), "f"(lo));
    return r;
}
__device__ __forceinline__ void mma16816(float* c, const uint32_t* a, const uint32_t* b) {
    asm volatile(
        "mma.sync.aligned.m16n8k16.row.col.f32.bf16.bf16.f32 "
        "{%0,%1,%2,%3}, {%4,%5,%6,%7}, {%8,%9}, {%0,%1,%2,%3};"
        : "+f"(c[0]), "+f"(c[1]), "+f"(c[2]), "+f"(c[3])
        : "r"(a[0]), "r"(a[1]), "r"(a[2]), "r"(a[3]), "r"(b[0]), "r"(b[1]));
}
__device__ __forceinline__ void mbar_init(unsigned mbar, unsigned count) {
    asm volatile("mbarrier.init.shared.b64 [%0], %1;" :: "r"(mbar), "r"(count) : "memory");
}
__device__ __forceinline__ void mbar_expect_tx(unsigned mbar, unsigned bytes) {
    asm volatile("mbarrier.arrive.expect_tx.shared.b64 _, [%0], %1;"
                 :: "r"(mbar), "r"(bytes) : "memory");
}
__device__ __forceinline__ void mbar_wait(unsigned mbar, unsigned parity) {
    asm volatile(
        "{\n\t"
        ".reg .pred P;\n\t"
        "W_%=:\n\t"
        "mbarrier.try_wait.parity.acquire.cta.shared::cta.b64 P, [%0], %1, 0x989680;\n\t"
        "@P bra D_%=;\n\t"
        "bra W_%=;\n\t"
        "D_%=:\n\t"
        "}"
        :: "r"(mbar), "r"(parity) : "memory");
}
__device__ __forceinline__ void bulk_g2s(unsigned dst, const void* src,
                                         unsigned bytes, unsigned mbar) {
    asm volatile(
        "cp.async.bulk.shared::cta.global.mbarrier::complete_tx::bytes "
        "[%0], [%1], %2, [%3];"
        :: "r"(dst), "l"(src), "r"(bytes), "r"(mbar) : "memory");
}
__device__ __forceinline__ void fence_async_shared() {
    asm volatile("fence.proxy.async.shared::cta;" ::: "memory");
}

__global__ __launch_bounds__(NTHR, 4) void qlinear_main(
    const float* __restrict__ x,
    const int*   __restrict__ w,
    const float* __restrict__ scale)
{
    extern __shared__ int sm[];
    // [0:32) mbarriers (2 x 8B used)
    int*      ws  = sm + 8;                     // 2 x WBUF ints (W, int32)
    uint32_t* xhw = (uint32_t*)(ws + 2 * WBUF); // x_hi plane (bf16x2)
    uint32_t* xlw = xhw + XWORDS;               // x_lo plane

    const unsigned smem_base = (unsigned)__cvta_generic_to_shared(sm);
    const unsigned mbar0 = smem_base;
    const unsigned mbar1 = smem_base + 8;
    const unsigned wsb   = smem_base + 32;      // W buffers base

    const int tid   = threadIdx.x;
    const int obase = blockIdx.x * OTILE;
    const int kbase = blockIdx.y * KC;

    // one bulk op per thread per stage: row `tid`, 64 B of k
    const int*     grow = w + (size_t)(obase + tid) * INF + kbase;
    const unsigned srow = wsb + (unsigned)tid * (WROW * 4);

    if (tid == 0) {
        mbar_init(mbar0, 1);
        mbar_init(mbar1, 1);
    }
    __syncthreads();   // mbarrier init visible before any complete_tx

    // prologue: issue stages 0,1
    if (tid == 0) {
        mbar_expect_tx(mbar0, STAGE_BYTES);
        mbar_expect_tx(mbar1, STAGE_BYTES);
    }
    fence_async_shared();
    bulk_g2s(srow,                grow,         KTILE * 4, mbar0);
    bulk_g2s(srow + WBUF * 4,     grow + KTILE, KTILE * 4, mbar1);

    // ---- stage x chunk as bf16 hi/lo planes ----
    {
        const int b   = tid >> 4;            // 0..15
        const int grp = tid & 15;            // 0..15 -> 8 k each
        const float* xp = x + (size_t)b * INF + kbase + grp * 8;
        uint32_t* xh = xhw + b * XSTR + grp * 4;
        uint32_t* xl = xlw + b * XSTR + grp * 4;
        #pragma unroll
        for (int q = 0; q < 2; ++q) {
            float4 v = ((const float4*)xp)[q];
            __nv_bfloat16 h0 = __float2bfloat16_rn(v.x);
            __nv_bfloat16 h1 = __float2bfloat16_rn(v.y);
            __nv_bfloat16 h2 = __float2bfloat16_rn(v.z);
            __nv_bfloat16 h3 = __float2bfloat16_rn(v.w);
            float l0 = v.x - __bfloat162float(h0);
            float l1 = v.y - __bfloat162float(h1);
            float l2 = v.z - __bfloat162float(h2);
            float l3 = v.w - __bfloat162float(h3);
            xh[q * 2]     = (uint32_t)__bfloat16_as_ushort(h0) |
                            ((uint32_t)__bfloat16_as_ushort(h1) << 16);
            xh[q * 2 + 1] = (uint32_t)__bfloat16_as_ushort(h2) |
                            ((uint32_t)__bfloat16_as_ushort(h3) << 16);
            xl[q * 2]     = pack_bf16x2(l0, l1);
            xl[q * 2 + 1] = pack_bf16x2(l2, l3);
        }
    }
    __syncthreads();   // x planes visible

    const int warp = tid >> 5;
    const int lane = tid & 31;
    const int g4   = lane >> 2;
    const int t4   = lane & 3;
    const int wofs = warp * 32;

    float acc[2][2][4];
    #pragma unroll
    for (int t = 0; t < 2; ++t)
        #pragma unroll
        for (int h = 0; h < 2; ++h)
            #pragma unroll
            for (int r = 0; r < 4; ++r) acc[t][h][r] = 0.f;

    #pragma unroll 1
    for (int s = 0; s < NSTAGE; ++s) {
        mbar_wait((s & 1) ? mbar1 : mbar0, (s >> 1) & 1);

        // ---- B fragments ----
        uint32_t bh[2][2], bl[2][2];
        #pragma unroll
        for (int h = 0; h < 2; ++h) {
            const int xrow = (g4 + 8 * h) * XSTR + 8 * s + t4;
            bh[h][0] = xhw[xrow];
            bh[h][1] = xhw[xrow + 4];
            bl[h][0] = xlw[xrow];
            bl[h][1] = xlw[xrow + 4];
        }

        const int* wbuf = ws + (s & 1) * WBUF;

        #pragma unroll
        for (int t = 0; t < 2; ++t) {
            const int r0 = wofs + t * 16 + g4;
            int2 w0 = *(const int2*)(wbuf + r0 * WROW + 2 * t4);
            int2 w1 = *(const int2*)(wbuf + (r0 + 8) * WROW + 2 * t4);
            int2 w2 = *(const int2*)(wbuf + r0 * WROW + 2 * t4 + 8);
            int2 w3 = *(const int2*)(wbuf + (r0 + 8) * WROW + 2 * t4 + 8);
            uint32_t a[4];
            a[0] = pack_bf16x2((float)w0.x, (float)w0.y);
            a[1] = pack_bf16x2((float)w1.x, (float)w1.y);
            a[2] = pack_bf16x2((float)w2.x, (float)w2.y);
            a[3] = pack_bf16x2((float)w3.x, (float)w3.y);
            mma16816(acc[t][0], a, bh[0]);
            mma16816(acc[t][0], a, bl[0]);
            mma16816(acc[t][1], a, bh[1]);
            mma16816(acc[t][1], a, bl[1]);
        }

        __syncthreads();   // all threads done reading buf[s&1]

        // issue stage s+2 into buf[s&1]
        if (s + 2 < NSTAGE) {
            const unsigned mb = (s & 1) ? mbar1 : mbar0;
            if (tid == 0) mbar_expect_tx(mb, STAGE_BYTES);
            fence_async_shared();
            bulk_g2s(srow + (unsigned)((s & 1) * WBUF * 4),
                     grow + (s + 2) * KTILE, KTILE * 4, mb);
        }
    }

    // ---- epilogue: scale, write split-K partials ----
    float* pp = g_partial + (size_t)blockIdx.y * BATCHN * OUTF;
    #pragma unroll
    for (int t = 0; t < 2; ++t) {
        const int r0 = obase + wofs + t * 16 + g4;
        const int r1 = r0 + 8;
        const float s0 = scale[r0];
        const float s1 = scale[r1];
        #pragma unroll
        for (int h = 0; h < 2; ++h) {
            const int b0 = 2 * t4 + 8 * h;
            pp[(size_t)b0       * OUTF + r0] = acc[t][h][0] * s0;
            pp[(size_t)(b0 + 1) * OUTF + r0] = acc[t][h][1] * s0;
            pp[(size_t)b0       * OUTF + r1] = acc[t][h][2] * s1;
            pp[(size_t)(b0 + 1) * OUTF + r1] = acc[t][h][3] * s1;
        }
    }
}

// Phase 1: 8 groups x (BATCHN*OUTF/4) float4 lanes; each thread sums 4 splits.
__global__ void qlinear_reduce1()
{
    const int n4 = BATCHN * OUTF / 4;        // 44032
    int t = blockIdx.x * blockDim.x + threadIdx.x;
    if (t >= 8 * n4) return;
    int g = t / n4;
    int i = t - g * n4;

    const float4* gp = (const float4*)g_partial + (size_t)(4 * g) * n4 + i;
    float4 s = make_float4(0.f, 0.f, 0.f, 0.f);
    #pragma unroll
    for (int ky = 0; ky < 4; ++ky) {
        float4 p = gp[(size_t)ky * n4];
        s.x += p.x; s.y += p.y; s.z += p.z; s.w += p.w;
    }
    ((float4*)g_p2)[(size_t)g * n4 + i] = s;
}

// Phase 2: sum 8 group-partials + bias -> out.
__global__ void qlinear_reduce2(const float* __restrict__ bias,
                                float* __restrict__ out)
{
    const int n4 = BATCHN * OUTF / 4;
    int i = blockIdx.x * blockDim.x + threadIdx.x;
    if (i >= n4) return;
    int o4 = i % (OUTF / 4);
    float4 s = ((const float4*)bias)[o4];
    const float4* gp = (const float4*)g_p2;
    #pragma unroll
    for (int g = 0; g < 8; ++g) {
        float4 p = gp[(size_t)g * n4 + i];
        s.x += p.x; s.y += p.y; s.z += p.z; s.w += p.w;
    }
    ((float4*)out)[i] = s;
}

extern "C" void kernel_launch(void* const* d_in, const int* in_sizes, int n_in,
                              void* d_out, int out_size)
{
    const float* x     = (const float*)d_in[0];
    const int*   w     = (const int*)  d_in[1];
    const float* scale = (const float*)d_in[2];
    const float* bias  = (const float*)d_in[3];
    float* out = (float*)d_out;

    cudaFuncSetAttribute(qlinear_main,
                         cudaFuncAttributeMaxDynamicSharedMemorySize, SMEM_BYTES);

    dim3 grid(OUTF / OTILE, SPLITK);   // (43, 32) = 1376 CTAs, 4/SM
    qlinear_main<<<grid, NTHR, SMEM_BYTES>>>(x, w, scale);

    int t1 = 8 * (BATCHN * OUTF / 4);
    qlinear_reduce1<<<(t1 + 255) / 256, 256>>>();

    int t2 = BATCHN * OUTF / 4;
    qlinear_reduce2<<<(t2 + 255) / 256, 256>>>(bias, out);
}

// round 11
// speedup vs baseline: 1.6072x; 1.6072x over previous
#include <cuda_runtime.h>
#include <cuda_bf16.h>
#include <cstdint>

#define OUTF   11008
#define INF    4096
#define BATCHN 16
#define SPLITK 16
#define KC     (INF / SPLITK)        // 256 k per CTA
#define KTILE  16                    // k per pipeline stage == one MMA k-step
#define NSTAGE (KC / KTILE)          // 16 stages
#define OTILE  128                   // output rows per CTA (8 warps x 16 rows)
#define NTHR   256
#define WROW   20                    // ints per smem W row (16 data + 4 pad)
#define WBUF   (OTILE * WROW)        // 2560 ints per buffer
#define XSTR   132                   // words per xs row (128 data + 4 pad)
#define XWORDS (16 * XSTR)           // 2112 words per plane
#define SMEM_BYTES ((2 * WBUF + 2 * XWORDS) * 4)   // 37376 B -> 4 CTAs/SM

// Split-K partials: [SPLITK][BATCHN][OUTF] = 11.25 MB
__device__ float g_partial[SPLITK * BATCHN * OUTF];
// Phase-1 reduced partials: [4][BATCHN][OUTF] = 2.8 MB
__device__ float g_p2[4 * BATCHN * OUTF];

__device__ __forceinline__ void cp_async16(unsigned smem_addr, const void* gptr) {
    asm volatile("cp.async.cg.shared.global [%0], [%1], 16;\n"
                 :: "r"(smem_addr), "l"(gptr));
}
__device__ __forceinline__ void cp_commit() {
    asm volatile("cp.async.commit_group;\n" ::: "memory");
}
__device__ __forceinline__ void cp_wait1() {
    asm volatile("cp.async.wait_group 1;\n" ::: "memory");
}
__device__ __forceinline__ uint32_t pack_bf16x2(float lo, float hi) {
    uint32_t r;
    asm("cvt.rn.bf16x2.f32 %0, %1, %2;" : "=r"(r) : "f"(hi), "f"(lo));
    return r;
}
__device__ __forceinline__ void mma16816(float* c, const uint32_t* a, const uint32_t* b) {
    asm volatile(
        "mma.sync.aligned.m16n8k16.row.col.f32.bf16.bf16.f32 "
        "{%0,%1,%2,%3}, {%4,%5,%6,%7}, {%8,%9}, {%0,%1,%2,%3};"
        : "+f"(c[0]), "+f"(c[1]), "+f"(c[2]), "+f"(c[3])
        : "r"(a[0]), "r"(a[1]), "r"(a[2]), "r"(a[3]), "r"(b[0]), "r"(b[1]));
}

__global__ __launch_bounds__(NTHR, 4) void qlinear_main(
    const float* __restrict__ x,
    const int*   __restrict__ w,
    const float* __restrict__ scale)
{
    extern __shared__ int sm[];
    int*      ws  = sm;                         // 2 x WBUF ints (W, int32)
    uint32_t* xhw = (uint32_t*)(sm + 2 * WBUF); // x_hi plane (bf16x2)
    uint32_t* xlw = xhw + XWORDS;               // x_lo plane

    const int tid   = threadIdx.x;
    const int warp  = tid >> 5;                 // 0..7, owns rows warp*16..+15
    const int lane  = tid & 31;
    const int obase = blockIdx.x * OTILE;
    const int kbase = blockIdx.y * KC;

    // ---- per-warp W staging: lane = (row r 0..7, chunk c 0..3); 2 ops cover 16 rows ----
    const int r = lane >> 2;
    const int c = lane & 3;
    const int wrow = warp * 16 + r;             // + 8 for second op
    const int* gw0 = w + (size_t)(obase + wrow) * INF + kbase + c * 4;
    const unsigned sw0 =
        (unsigned)__cvta_generic_to_shared(ws + wrow * WROW + c * 4);

    // prologue: issue stages 0,1 into buffers 0,1 (per-warp groups)
    #pragma unroll
    for (int s = 0; s < 2; ++s) {
        const unsigned sd = sw0 + (unsigned)(s * WBUF * 4);
        cp_async16(sd,                          gw0 + s * KTILE);
        cp_async16(sd + 8u * WROW * 4,          gw0 + s * KTILE + (size_t)8 * INF);
        cp_commit();
    }

    // ---- stage x chunk as bf16 hi/lo planes (CTA-wide, once) ----
    {
        const int b   = tid >> 4;            // 0..15
        const int grp = tid & 15;            // 0..15 -> 16 k each
        const float* xp = x + (size_t)b * INF + kbase + grp * 16;
        uint32_t* xh = xhw + b * XSTR + grp * 8;
        uint32_t* xl = xlw + b * XSTR + grp * 8;
        #pragma unroll
        for (int q = 0; q < 4; ++q) {
            float4 v = ((const float4*)xp)[q];
            __nv_bfloat16 h0 = __float2bfloat16_rn(v.x);
            __nv_bfloat16 h1 = __float2bfloat16_rn(v.y);
            __nv_bfloat16 h2 = __float2bfloat16_rn(v.z);
            __nv_bfloat16 h3 = __float2bfloat16_rn(v.w);
            float l0 = v.x - __bfloat162float(h0);
            float l1 = v.y - __bfloat162float(h1);
            float l2 = v.z - __bfloat162float(h2);
            float l3 = v.w - __bfloat162float(h3);
            xh[q * 2]     = (uint32_t)__bfloat16_as_ushort(h0) |
                            ((uint32_t)__bfloat16_as_ushort(h1) << 16);
            xh[q * 2 + 1] = (uint32_t)__bfloat16_as_ushort(h2) |
                            ((uint32_t)__bfloat16_as_ushort(h3) << 16);
            xl[q * 2]     = pack_bf16x2(l0, l1);
            xl[q * 2 + 1] = pack_bf16x2(l2, l3);
        }
    }
    __syncthreads();   // x planes visible to all warps; after this, warps free-run

    const int g4 = lane >> 2;
    const int t4 = lane & 3;

    float acc[2][4];                         // [batch-half][c-regs]
    #pragma unroll
    for (int h = 0; h < 2; ++h)
        #pragma unroll
        for (int q = 0; q < 4; ++q) acc[h][q] = 0.f;

    #pragma unroll 1
    for (int s = 0; s < NSTAGE; ++s) {
        cp_wait1();        // this lane's stage-s copies complete
        __syncwarp();      // all lanes' stage-s copies complete & visible

        // ---- B fragments: x_hi / x_lo, both batch halves ----
        uint32_t bh[2][2], bl[2][2];
        #pragma unroll
        for (int h = 0; h < 2; ++h) {
            const int xrow = (g4 + 8 * h) * XSTR + 8 * s + t4;
            bh[h][0] = xhw[xrow];
            bh[h][1] = xhw[xrow + 4];
            bl[h][0] = xlw[xrow];
            bl[h][1] = xlw[xrow + 4];
        }

        // ---- A fragment from this warp's 16 rows ----
        const int* wr = ws + (s & 1) * WBUF + (warp * 16 + g4) * WROW + 2 * t4;
        int2 w0 = *(const int2*)(wr);                    // row g4,   k 2t4..
        int2 w1 = *(const int2*)(wr + 8 * WROW);         // row g4+8, k 2t4..
        int2 w2 = *(const int2*)(wr + 8);                // row g4,   k 2t4+8..
        int2 w3 = *(const int2*)(wr + 8 * WROW + 8);     // row g4+8, k 2t4+8..
        uint32_t a[4];
        a[0] = pack_bf16x2((float)w0.x, (float)w0.y);
        a[1] = pack_bf16x2((float)w1.x, (float)w1.y);
        a[2] = pack_bf16x2((float)w2.x, (float)w2.y);
        a[3] = pack_bf16x2((float)w3.x, (float)w3.y);

        mma16816(acc[0], a, bh[0]);
        mma16816(acc[0], a, bl[0]);
        mma16816(acc[1], a, bh[1]);
        mma16816(acc[1], a, bl[1]);

        __syncwarp();      // all lanes done reading buf[s&1] before overwrite

        // issue stage s+2 into buf[s&1]; always commit for exact group accounting
        if (s + 2 < NSTAGE) {
            const unsigned sd = sw0 + (unsigned)((s & 1) * WBUF * 4);
            cp_async16(sd,                 gw0 + (s + 2) * KTILE);
            cp_async16(sd + 8u * WROW * 4, gw0 + (s + 2) * KTILE + (size_t)8 * INF);
        }
        cp_commit();
    }

    // ---- epilogue: scale, write split-K partials ----
    float* pp = g_partial + (size_t)blockIdx.y * BATCHN * OUTF;
    const int r0 = obase + warp * 16 + g4;
    const int r1 = r0 + 8;
    const float s0 = scale[r0];
    const float s1 = scale[r1];
    #pragma unroll
    for (int h = 0; h < 2; ++h) {
        const int b0 = 2 * t4 + 8 * h;
        pp[(size_t)b0       * OUTF + r0] = acc[h][0] * s0;
        pp[(size_t)(b0 + 1) * OUTF + r0] = acc[h][1] * s0;
        pp[(size_t)b0       * OUTF + r1] = acc[h][2] * s1;
        pp[(size_t)(b0 + 1) * OUTF + r1] = acc[h][3] * s1;
    }
}

// Phase 1: 4 groups x (BATCHN*OUTF/4) float4 lanes; each thread sums 4 splits.
__global__ void qlinear_reduce1()
{
    const int n4 = BATCHN * OUTF / 4;        // 44032
    int t = blockIdx.x * blockDim.x + threadIdx.x;
    if (t >= 4 * n4) return;
    int g = t / n4;                          // split group 0..3
    int i = t - g * n4;

    const float4* gp = (const float4*)g_partial + (size_t)(4 * g) * n4 + i;
    float4 s = make_float4(0.f, 0.f, 0.f, 0.f);
    #pragma unroll
    for (int ky = 0; ky < 4; ++ky) {
        float4 p = gp[(size_t)ky * n4];
        s.x += p.x; s.y += p.y; s.z += p.z; s.w += p.w;
    }
    ((float4*)g_p2)[(size_t)g * n4 + i] = s;
}

// Phase 2: sum 4 group-partials + bias -> out.
__global__ void qlinear_reduce2(const float* __restrict__ bias,
                                float* __restrict__ out)
{
    const int n4 = BATCHN * OUTF / 4;
    int i = blockIdx.x * blockDim.x + threadIdx.x;
    if (i >= n4) return;
    int o4 = i % (OUTF / 4);
    float4 s = ((const float4*)bias)[o4];
    const float4* gp = (const float4*)g_p2;
    #pragma unroll
    for (int g = 0; g < 4; ++g) {
        float4 p = gp[(size_t)g * n4 + i];
        s.x += p.x; s.y += p.y; s.z += p.z; s.w += p.w;
    }
    ((float4*)out)[i] = s;
}

extern "C" void kernel_launch(void* const* d_in, const int* in_sizes, int n_in,
                              void* d_out, int out_size)
{
    const float* x     = (const float*)d_in[0];
    const int*   w     = (const int*)  d_in[1];
    const float* scale = (const float*)d_in[2];
    const float* bias  = (const float*)d_in[3];
    float* out = (float*)d_out;

    cudaFuncSetAttribute(qlinear_main,
                         cudaFuncAttributeMaxDynamicSharedMemorySize, SMEM_BYTES);

    dim3 grid(OUTF / OTILE, SPLITK);   // (86, 16) = 1376 CTAs, 4/SM
    qlinear_main<<<grid, NTHR, SMEM_BYTES>>>(x, w, scale);

    int t1 = 4 * (BATCHN * OUTF / 4);
    qlinear_reduce1<<<(t1 + 255) / 256, 256>>>();

    int t2 = BATCHN * OUTF / 4;
    qlinear_reduce2<<<(t2 + 255) / 256, 256>>>(bias, out);
}

// round 13
// speedup vs baseline: 1.7247x; 1.0732x over previous
#include <cuda_runtime.h>
#include <cuda_bf16.h>
#include <cstdint>

#define OUTF   11008
#define INF    4096
#define BATCHN 16
#define SPLITK 16
#define KC     (INF / SPLITK)        // 256 k per CTA
#define KTILE  16                    // k per pipeline stage == one MMA k-step
#define NSTAGE (KC / KTILE)          // 16 stages
#define NBUF   3
#define OTILE  128                   // output rows per CTA (8 warps x 16 rows)
#define NTHR   256
#define WROW   20                    // ints per smem W row (16 data + 4 pad)
#define WBUF   (OTILE * WROW)        // 2560 ints per buffer
#define XSTR   132                   // words per xs row (128 data + 4 pad)
#define XWORDS (16 * XSTR)           // 2112 words per plane
#define SMEM_BYTES ((NBUF * WBUF + 2 * XWORDS) * 4)   // 30720+16896 = 47616 -> 4 CTAs/SM

__device__ __forceinline__ void cp_async16(unsigned smem_addr, const void* gptr) {
    asm volatile("cp.async.cg.shared.global [%0], [%1], 16;\n"
                 :: "r"(smem_addr), "l"(gptr));
}
__device__ __forceinline__ void cp_commit() {
    asm volatile("cp.async.commit_group;\n" ::: "memory");
}
__device__ __forceinline__ void cp_wait1() {
    asm volatile("cp.async.wait_group 1;\n" ::: "memory");
}
__device__ __forceinline__ uint32_t pack_bf16x2(float lo, float hi) {
    uint32_t r;
    asm("cvt.rn.bf16x2.f32 %0, %1, %2;" : "=r"(r) : "f"(hi), "f"(lo));
    return r;
}
__device__ __forceinline__ void mma16816(float* c, const uint32_t* a, const uint32_t* b) {
    asm volatile(
        "mma.sync.aligned.m16n8k16.row.col.f32.bf16.bf16.f32 "
        "{%0,%1,%2,%3}, {%4,%5,%6,%7}, {%8,%9}, {%0,%1,%2,%3};"
        : "+f"(c[0]), "+f"(c[1]), "+f"(c[2]), "+f"(c[3])
        : "r"(a[0]), "r"(a[1]), "r"(a[2]), "r"(a[3]), "r"(b[0]), "r"(b[1]));
}

// init: out[b][o] = bias[o]  (float4 vectorized)
__global__ void qlinear_init(const float* __restrict__ bias,
                             float* __restrict__ out)
{
    const int n4 = BATCHN * OUTF / 4;
    int i = blockIdx.x * blockDim.x + threadIdx.x;
    if (i >= n4) return;
    ((float4*)out)[i] = ((const float4*)bias)[i % (OUTF / 4)];
}

__global__ __launch_bounds__(NTHR, 4) void qlinear_main(
    const float* __restrict__ x,
    const int*   __restrict__ w,
    const float* __restrict__ scale,
    float* __restrict__ out)
{
    extern __shared__ int sm[];
    int*      ws  = sm;                            // NBUF x WBUF ints (W, int32)
    uint32_t* xhw = (uint32_t*)(sm + NBUF * WBUF); // x_hi plane (bf16x2)
    uint32_t* xlw = xhw + XWORDS;                  // x_lo plane

    const int tid   = threadIdx.x;
    const int warp  = tid >> 5;                 // 0..7, owns rows warp*16..+15
    const int lane  = tid & 31;
    const int obase = blockIdx.x * OTILE;
    const int kbase = blockIdx.y * KC;

    // ---- per-warp W staging: lane = (row r 0..7, chunk c 0..3); 2 ops cover 16 rows ----
    const int r = lane >> 2;
    const int c = lane & 3;
    const int wrow = warp * 16 + r;             // + 8 for second op
    const int* gw0 = w + (size_t)(obase + wrow) * INF + kbase + c * 4;
    const unsigned sw0 =
        (unsigned)__cvta_generic_to_shared(ws + wrow * WROW + c * 4);

    // prologue: issue stages 0,1 into buffers 0,1 (per-warp groups)
    #pragma unroll
    for (int s = 0; s < 2; ++s) {
        const unsigned sd = sw0 + (unsigned)(s * WBUF * 4);
        cp_async16(sd,                 gw0 + s * KTILE);
        cp_async16(sd + 8u * WROW * 4, gw0 + s * KTILE + (size_t)8 * INF);
        cp_commit();
    }

    // ---- stage x chunk as bf16 hi/lo planes (CTA-wide, once) ----
    {
        const int b   = tid >> 4;            // 0..15
        const int grp = tid & 15;            // 0..15 -> 16 k each
        const float* xp = x + (size_t)b * INF + kbase + grp * 16;
        uint32_t* xh = xhw + b * XSTR + grp * 8;
        uint32_t* xl = xlw + b * XSTR + grp * 8;
        #pragma unroll
        for (int q = 0; q < 4; ++q) {
            float4 v = ((const float4*)xp)[q];
            __nv_bfloat16 h0 = __float2bfloat16_rn(v.x);
            __nv_bfloat16 h1 = __float2bfloat16_rn(v.y);
            __nv_bfloat16 h2 = __float2bfloat16_rn(v.z);
            __nv_bfloat16 h3 = __float2bfloat16_rn(v.w);
            float l0 = v.x - __bfloat162float(h0);
            float l1 = v.y - __bfloat162float(h1);
            float l2 = v.z - __bfloat162float(h2);
            float l3 = v.w - __bfloat162float(h3);
            xh[q * 2]     = (uint32_t)__bfloat16_as_ushort(h0) |
                            ((uint32_t)__bfloat16_as_ushort(h1) << 16);
            xh[q * 2 + 1] = (uint32_t)__bfloat16_as_ushort(h2) |
                            ((uint32_t)__bfloat16_as_ushort(h3) << 16);
            xl[q * 2]     = pack_bf16x2(l0, l1);
            xl[q * 2 + 1] = pack_bf16x2(l2, l3);
        }
    }
    __syncthreads();   // x planes visible to all warps; after this, warps free-run

    const int g4 = lane >> 2;
    const int t4 = lane & 3;

    float acc[2][4];                         // [batch-half][c-regs]
    #pragma unroll
    for (int h = 0; h < 2; ++h)
        #pragma unroll
        for (int q = 0; q < 4; ++q) acc[h][q] = 0.f;

    int bcur = 0;                            // s % 3
    #pragma unroll 1
    for (int s = 0; s < NSTAGE; ++s) {
        cp_wait1();        // stage s copies complete (only s+1 pending)
        __syncwarp();

        // issue stage s+2 into buf[(s+2)%3] BEFORE compute (buffer free since s-1)
        const int bnxt = (bcur + 2 >= NBUF) ? (bcur + 2 - NBUF) : (bcur + 2);
        if (s + 2 < NSTAGE) {
            const unsigned sd = sw0 + (unsigned)(bnxt * WBUF * 4);
            cp_async16(sd,                 gw0 + (s + 2) * KTILE);
            cp_async16(sd + 8u * WROW * 4, gw0 + (s + 2) * KTILE + (size_t)8 * INF);
        }
        cp_commit();       // always commit for exact group accounting

        // ---- B fragments: x_hi / x_lo, both batch halves ----
        uint32_t bh[2][2], bl[2][2];
        #pragma unroll
        for (int h = 0; h < 2; ++h) {
            const int xrow = (g4 + 8 * h) * XSTR + 8 * s + t4;
            bh[h][0] = xhw[xrow];
            bh[h][1] = xhw[xrow + 4];
            bl[h][0] = xlw[xrow];
            bl[h][1] = xlw[xrow + 4];
        }

        // ---- A fragment from this warp's 16 rows ----
        const int* wr = ws + bcur * WBUF + (warp * 16 + g4) * WROW + 2 * t4;
        int2 w0 = *(const int2*)(wr);
        int2 w1 = *(const int2*)(wr + 8 * WROW);
        int2 w2 = *(const int2*)(wr + 8);
        int2 w3 = *(const int2*)(wr + 8 * WROW + 8);
        uint32_t a[4];
        a[0] = pack_bf16x2((float)w0.x, (float)w0.y);
        a[1] = pack_bf16x2((float)w1.x, (float)w1.y);
        a[2] = pack_bf16x2((float)w2.x, (float)w2.y);
        a[3] = pack_bf16x2((float)w3.x, (float)w3.y);

        mma16816(acc[0], a, bh[0]);
        mma16816(acc[0], a, bl[0]);
        mma16816(acc[1], a, bh[1]);
        mma16816(acc[1], a, bl[1]);

        __syncwarp();      // all lanes done reading buf[bcur] before it is re-targeted

        bcur = (bcur + 1 >= NBUF) ? 0 : (bcur + 1);
    }

    // ---- epilogue: scale + atomic accumulate into out (bias pre-initialized) ----
    const int r0 = obase + warp * 16 + g4;
    const int r1 = r0 + 8;
    const float s0 = scale[r0];
    const float s1 = scale[r1];
    #pragma unroll
    for (int h = 0; h < 2; ++h) {
        const int b0 = 2 * t4 + 8 * h;
        atomicAdd(out + (size_t)b0       * OUTF + r0, acc[h][0] * s0);
        atomicAdd(out + (size_t)(b0 + 1) * OUTF + r0, acc[h][1] * s0);
        atomicAdd(out + (size_t)b0       * OUTF + r1, acc[h][2] * s1);
        atomicAdd(out + (size_t)(b0 + 1) * OUTF + r1, acc[h][3] * s1);
    }
}

extern "C" void kernel_launch(void* const* d_in, const int* in_sizes, int n_in,
                              void* d_out, int out_size)
{
    const float* x     = (const float*)d_in[0];
    const int*   w     = (const int*)  d_in[1];
    const float* scale = (const float*)d_in[2];
    const float* bias  = (const float*)d_in[3];
    float* out = (float*)d_out;

    cudaFuncSetAttribute(qlinear_main,
                         cudaFuncAttributeMaxDynamicSharedMemorySize, SMEM_BYTES);

    int n4 = BATCHN * OUTF / 4;
    qlinear_init<<<(n4 + 255) / 256, 256>>>(bias, out);

    dim3 grid(OUTF / OTILE, SPLITK);   // (86, 16) = 1376 CTAs, 4/SM
    qlinear_main<<<grid, NTHR, SMEM_BYTES>>>(x, w, scale, out);
}